// round 15
// baseline (speedup 1.0000x reference)
#include <cuda_runtime.h>
#include <cuda_bf16.h>
#include <math.h>
#include <stdint.h>

#define Bn   8
#define Gn   1024
#define Mn   8
#define Nn   2048
#define RBFn 50
#define QCH  13     // 13 chunks of 4 r (52 padded)
#define NPAIR 28    // i<j pairs of 8 particles
#define Hn   128
#define Fn   3200
#define Tn   8      // (b,g) pairs per CTA in main kernel
#define KROW 424    // smv row stride per k: 53*8 floats
#define XC_ROWS 32
#define XC_CHUNK 512
#define LSE_CH  32

// ---- main-kernel smem layout (bytes) ----
#define WB_K      26624                 // one pair's weights: 13*128*16 B
#define SMV_BYTES (NPAIR * KROW * 4)    // 47488
#define DL_OFF    SMV_BYTES             // 47488 (28*24 floats = 2688 B)
#define XCS_OFF   (DL_OFF + NPAIR * 96) // 50176 (192 floats = 768 B)
#define WBUF_OFF  (XCS_OFF + 768)       // 50944 (16B aligned)
#define MBAR_OFF  (WBUF_OFF + 2 * WB_K) // 104192
#define SMEM_MAIN_TOTAL (MBAR_OFF + 32) // 104224

// f32x2 packed math helpers
#define FMA2(d, a, b, c) \
    asm("fma.rn.f32x2 %0, %1, %2, %3;" : "=l"(d) : "l"(a), "l"(b), "l"(c))
#define PK2(d, x) \
    asm("mov.b64 %0, {%1, %1};" : "=l"(d) : "f"(x))
#define UNPK2(lo, hi, v) \
    asm("mov.b64 {%0, %1}, %2;" : "=f"(lo), "=f"(hi) : "l"(v))

// bf16 (packed in u32) -> f32
#define BFLO(u) __uint_as_float((u) << 16)
#define BFHI(u) __uint_as_float((u) & 0xFFFF0000u)

// ---- async copy / mbarrier helpers (verified to compile on this harness) ----
__device__ __forceinline__ uint32_t smem_u32(const void* p) {
    uint32_t a;
    asm("{ .reg .u64 t; cvta.to.shared.u64 t, %1; cvt.u32.u64 %0, t; }" : "=r"(a) : "l"(p));
    return a;
}
#define MBAR_INIT(addr, cnt) \
    asm volatile("mbarrier.init.shared.b64 [%0], %1;" :: "r"(addr), "r"((uint32_t)(cnt)) : "memory")
#define MBAR_EXPECT_TX(addr, bytes) \
    asm volatile("mbarrier.arrive.expect_tx.shared.b64 _, [%0], %1;" :: "r"(addr), "r"((uint32_t)(bytes)) : "memory")
#define MBAR_WAIT(addr, parity) do { \
    uint32_t _m = (addr); uint32_t _p = (parity); uint32_t _ok; \
    asm volatile("{\n\t.reg .pred p;\n\tmbarrier.try_wait.parity.shared.b64 p, [%1], %2;\n\tselp.b32 %0,1,0,p;\n\t}" \
        : "=r"(_ok) : "r"(_m), "r"(_p) : "memory"); \
    if (!_ok) { \
        asm volatile("{\n\t.reg .pred P1;\n\tWL%=:\n\tmbarrier.try_wait.parity.shared.b64 P1, [%0], %1, 0x989680;\n\t@P1 bra.uni WD%=;\n\tbra.uni WL%=;\n\tWD%=:\n\t}" \
            :: "r"(_m), "r"(_p) : "memory"); \
    } \
} while (0)
#define BULK_G2S(dst, src, bytes, mbar) \
    asm volatile("cp.async.bulk.shared::cluster.global.mbarrier::complete_tx::bytes [%0], [%1], %2, [%3];" \
        :: "r"(dst), "l"(src), "r"((uint32_t)(bytes)), "r"(mbar) : "memory")
#define FENCE_PROXY() asm volatile("fence.proxy.async;" ::: "memory")

__constant__ int c_pi[NPAIR] = {0,0,0,0,0,0,0, 1,1,1,1,1,1, 2,2,2,2,2, 3,3,3,3, 4,4,4, 5,5, 6};
__constant__ int c_pj[NPAIR] = {1,2,3,4,5,6,7, 2,3,4,5,6,7, 3,4,5,6,7, 4,5,6,7, 5,6,7, 6,7, 7};

// -------------------- scratch (static device globals) --------------------
// bf16 folded weights, L/R interleaved: [k(28)][q(13)][h(128)] as uint4
__device__ __align__(16) uint4 g_Wbf[NPAIR * QCH * Hn];
__device__ float g_xc[Bn * Gn * Mn * 3];
__device__ float g_att[Bn * Gn * Hn];
__device__ float g_lsem[Bn * LSE_CH * Hn];
__device__ float g_lses[Bn * LSE_CH * Hn];

// ---------- kernel 1: fold + repack weights to interleaved bf16 ----------
__global__ void __launch_bounds__(128)
pad_weights_kernel(const float* __restrict__ WL, const float* __restrict__ WR) {
    int kq = blockIdx.x;              // 0..363
    int k  = kq / QCH;
    int q  = kq - k * QCH;
    int h  = threadIdx.x;
    int i  = c_pi[k], j = c_pj[k];
    float vL[4], vR[4];
    #pragma unroll
    for (int rr = 0; rr < 4; rr++) {
        int r = q * 4 + rr;
        vL[rr] = 0.f; vR[rr] = 0.f;
        if (r < RBFn) {
            int fij = (i * Mn + j) * RBFn + r;
            int fji = (j * Mn + i) * RBFn + r;
            vL[rr] = WL[h * Fn + fij] - WL[h * Fn + fji];
            vR[rr] = WR[h * Fn + fij] - WR[h * Fn + fji];
        }
    }
    __nv_bfloat162 lx = __floats2bfloat162_rn(vL[0], vL[1]);
    __nv_bfloat162 ly = __floats2bfloat162_rn(vL[2], vL[3]);
    __nv_bfloat162 rx = __floats2bfloat162_rn(vR[0], vR[1]);
    __nv_bfloat162 ry = __floats2bfloat162_rn(vR[2], vR[3]);
    uint4 o;
    o.x = *(unsigned int*)&lx;
    o.y = *(unsigned int*)&ly;
    o.z = *(unsigned int*)&rx;
    o.w = *(unsigned int*)&ry;
    g_Wbf[kq * Hn + h] = o;
}

// ---------- kernel 2: xc = batched thin GEMM (f32x2, chunked) ----------
__global__ void __launch_bounds__(XC_ROWS * 12, 2)
xc_kernel(const float* __restrict__ x, const float* __restrict__ Wmap) {
    extern __shared__ float xs[];  // [XC_CHUNK][24] = 49152 B

    int row = blockIdx.x * XC_ROWS + threadIdx.x / 12;
    int c2  = threadIdx.x % 12;

    const float4* __restrict__ wrow =
        reinterpret_cast<const float4*>(Wmap) + (size_t)row * (Nn / 4);

    unsigned long long a0 = 0ull, a1 = 0ull, a2 = 0ull, a3 = 0ull;

    for (int ch = 0; ch < Nn / XC_CHUNK; ch++) {
        __syncthreads();
        for (int e = threadIdx.x; e < Bn * XC_CHUNK * 3; e += XC_ROWS * 12) {
            int b   = e / (XC_CHUNK * 3);
            int rem = e - b * (XC_CHUNK * 3);
            int n   = rem / 3;
            int d   = rem - n * 3;
            xs[n * 24 + b * 3 + d] = x[(b * Nn + ch * XC_CHUNK + n) * 3 + d];
        }
        __syncthreads();

        const float4* wch = wrow + ch * (XC_CHUNK / 4);
        #pragma unroll 8
        for (int n4 = 0; n4 < XC_CHUNK / 4; n4++) {
            float4 w = __ldg(wch + n4);
            const float* xp = xs + n4 * 96 + c2 * 2;
            unsigned long long s0 = *(const unsigned long long*)(xp);
            unsigned long long s1 = *(const unsigned long long*)(xp + 24);
            unsigned long long s2 = *(const unsigned long long*)(xp + 48);
            unsigned long long s3 = *(const unsigned long long*)(xp + 72);
            unsigned long long w0, w1, w2, w3;
            PK2(w0, w.x); PK2(w1, w.y); PK2(w2, w.z); PK2(w3, w.w);
            FMA2(a0, w0, s0, a0);
            FMA2(a1, w1, s1, a1);
            FMA2(a2, w2, s2, a2);
            FMA2(a3, w3, s3, a3);
        }
    }

    float a0lo, a0hi, a1lo, a1hi, a2lo, a2hi, a3lo, a3hi;
    UNPK2(a0lo, a0hi, a0);
    UNPK2(a1lo, a1hi, a1);
    UNPK2(a2lo, a2hi, a2);
    UNPK2(a3lo, a3hi, a3);
    float accA = (a0lo + a1lo) + (a2lo + a3lo);
    float accB = (a0hi + a1hi) + (a2hi + a3hi);

    int cA = c2 * 2;
    int bA = cA / 3, dA = cA - bA * 3;
    g_xc[((size_t)bA * (Gn * Mn) + row) * 3 + dA] = accA;
    int cB = cA + 1;
    int bB = cB / 3, dB = cB - bB * 3;
    g_xc[((size_t)bB * (Gn * Mn) + row) * 3 + dB] = accB;
}

// -------------------- kernel 3: main fused kernel --------------------
// 256 threads = h(128) x t-half(2); 2 CTA/SM. Weights streamed into smem
// (double-buffered cp.async.bulk, one 26.6KB block per pair k); all threads
// consume pair k from smem (conflict-free LDS), so the k-sequential stream
// works and the epilogue is thread-local (no cross-thread combine).
__global__ void __launch_bounds__(256, 2)
main_kernel(float MU0f, float DMf, float INVDMf, float BETAf,
            float TBDf, float BDM2f, float D2f) {
    extern __shared__ char smc[];
    float* smv = (float*)smc;                  // 28*424 floats
    float* dl  = (float*)(smc + DL_OFF);       // 28*24 floats
    float* xcs = (float*)(smc + XCS_OFF);      // 192 floats
    uint32_t sb = smem_u32(smc);

    int tid = threadIdx.x;
    int bg0 = blockIdx.x * Tn;

    if (tid == 0) {
        MBAR_INIT(sb + MBAR_OFF + 0, 1);
        MBAR_INIT(sb + MBAR_OFF + 8, 1);
        FENCE_PROXY();
    }
    for (int e = tid; e < Tn * 24; e += blockDim.x)
        xcs[e] = g_xc[bg0 * 24 + e];
    __syncthreads();   // mbar init + xcs visible

    if (tid == 0) {    // prefetch weights for pairs 0 and 1 (overlaps Phase A)
        MBAR_EXPECT_TX(sb + MBAR_OFF + 0, WB_K);
        BULK_G2S(sb + WBUF_OFF, (const void*)(g_Wbf), WB_K, sb + MBAR_OFF + 0);
        MBAR_EXPECT_TX(sb + MBAR_OFF + 8, WB_K);
        BULK_G2S(sb + WBUF_OFF + WB_K, (const void*)(g_Wbf + QCH * Hn), WB_K,
                 sb + MBAR_OFF + 8);
    }

    // ---- Phase A: thread = (k, t); geometric recurrence from peak ----
    if (tid < Tn * NPAIR) {
        int k = tid >> 3;
        int t = tid & 7;
        int i = c_pi[k], j = c_pj[k];
        const float* xt = xcs + t * 24;
        float dx = xt[j * 3 + 0] - xt[i * 3 + 0];
        float dy = xt[j * 3 + 1] - xt[i * 3 + 1];
        float dz = xt[j * 3 + 2] - xt[i * 3 + 2];
        float* drow = dl + k * 24 + t;
        drow[0]  = dx;
        drow[8]  = dy;
        drow[16] = dz;

        float dn  = sqrtf(fmaf(dx, dx, fmaf(dy, dy, dz * dz)) + 1e-5f);
        float uu  = __expf(-dn);
        float cut = (dn < 5.0f)
                  ? 0.5f * (__cosf(dn * 0.6283185307179586f) + 1.0f)
                  : 0.0f;
        float dd   = dn + 1e-5f;
        float coef = cut / (dd * dd);

        float up = uu - MU0f;
        int rs = (int)rintf(up * INVDMf);
        rs = rs < 0 ? 0 : (rs > 49 ? 49 : rs);
        float du = up - (float)rs * DMf;
        float t0 = coef * __expf(-BETAf * du * du);
        float s  = TBDf * up - BDM2f * (float)(2 * rs + 1);
        float qu = __expf(s);
        float qd = __expf(-s) * D2f;

        float* srow = smv + k * KROW + t;
        srow[rs * 8] = t0;
        float tv = t0;
        for (int r = rs + 1; r < RBFn; r++) {
            tv *= qu; qu *= D2f;
            srow[r * 8] = tv;
        }
        tv = t0;
        for (int r = rs - 1; r >= 0; r--) {
            tv *= qd; qd *= D2f;
            srow[r * 8] = tv;
        }
        srow[50 * 8] = 0.f;
        srow[51 * 8] = 0.f;
    }
    __syncthreads();

    // ---- Phase B: stream pairs; each thread owns 4 t, both L and R ----
    int h  = tid & 127;
    int ph = tid >> 7;          // t-half: t in [ph*4, ph*4+4)

    unsigned long long acc2L[2][3] = {{0ull}}, acc2R[2][3] = {{0ull}};

    for (int k = 0; k < NPAIR; k++) {
        MBAR_WAIT(sb + MBAR_OFF + (k & 1) * 8, (k >> 1) & 1);

        const uint4* wk = (const uint4*)(smc + WBUF_OFF + (k & 1) * WB_K);
        const float* sk = smv + k * KROW + ph * 4;

        unsigned long long ws2L[2] = {0ull, 0ull};
        unsigned long long ws2R[2] = {0ull, 0ull};

        #pragma unroll
        for (int q = 0; q < QCH; q++) {
            uint4 wp = wk[q * Hn + h];

            #define DO_RR(RR, AV, CV)                                          \
            {                                                                  \
                ulonglong2 s = *(const ulonglong2*)(sk + (q * 4 + (RR)) * 8);  \
                unsigned long long a2, c2;                                     \
                PK2(a2, (AV)); PK2(c2, (CV));                                  \
                FMA2(ws2L[0], a2, s.x, ws2L[0]);                               \
                FMA2(ws2L[1], a2, s.y, ws2L[1]);                               \
                FMA2(ws2R[0], c2, s.x, ws2R[0]);                               \
                FMA2(ws2R[1], c2, s.y, ws2R[1]);                               \
            }
            DO_RR(0, BFLO(wp.x), BFLO(wp.z))
            DO_RR(1, BFHI(wp.x), BFHI(wp.z))
            DO_RR(2, BFLO(wp.y), BFLO(wp.w))
            DO_RR(3, BFHI(wp.y), BFHI(wp.w))
            #undef DO_RR
        }

        const float* dk = dl + k * 24 + ph * 4;
        #pragma unroll
        for (int d = 0; d < 3; d++) {
            ulonglong2 dd = *(const ulonglong2*)(dk + d * 8);
            FMA2(acc2L[0][d], ws2L[0], dd.x, acc2L[0][d]);
            FMA2(acc2L[1][d], ws2L[1], dd.y, acc2L[1][d]);
            FMA2(acc2R[0][d], ws2R[0], dd.x, acc2R[0][d]);
            FMA2(acc2R[1][d], ws2R[1], dd.y, acc2R[1][d]);
        }

        __syncthreads();    // all consumers done with buffer (k&1)
        if (tid == 0 && k + 2 < NPAIR) {
            MBAR_EXPECT_TX(sb + MBAR_OFF + (k & 1) * 8, WB_K);
            BULK_G2S(sb + WBUF_OFF + (k & 1) * WB_K,
                     (const void*)(g_Wbf + (k + 2) * QCH * Hn), WB_K,
                     sb + MBAR_OFF + (k & 1) * 8);
        }
    }

    // ---- direct epilogue: att = L . R for this thread's 4 t ----
    #pragma unroll
    for (int u = 0; u < 2; u++) {
        float L[2][3], R[2][3];
        #pragma unroll
        for (int d = 0; d < 3; d++) {
            UNPK2(L[0][d], L[1][d], acc2L[u][d]);
            UNPK2(R[0][d], R[1][d], acc2R[u][d]);
        }
        #pragma unroll
        for (int e = 0; e < 2; e++) {
            int tt = ph * 4 + 2 * u + e;
            float att = fmaf(L[e][0], R[e][0],
                        fmaf(L[e][1], R[e][1],
                             L[e][2] * R[e][2])) + 1e-5f;
            g_att[(size_t)(bg0 + tt) * Hn + h] = att;
        }
    }
}

// ---------- kernel 4a: partial logsumexp ----------
__global__ void __launch_bounds__(128)
lse_partial_kernel() {
    int b  = blockIdx.y;
    int ch = blockIdx.x;
    int h  = threadIdx.x;
    const int GPC = Gn / LSE_CH;
    const float* base = g_att + ((size_t)b * Gn + ch * GPC) * Hn + h;

    float v[GPC];
    #pragma unroll
    for (int i = 0; i < GPC; i++) v[i] = base[(size_t)i * Hn];

    float mx = v[0];
    #pragma unroll
    for (int i = 1; i < GPC; i++) mx = fmaxf(mx, v[i]);
    float s = 0.f;
    #pragma unroll
    for (int i = 0; i < GPC; i++) s += __expf(v[i] - mx);

    g_lsem[(b * LSE_CH + ch) * Hn + h] = mx;
    g_lses[(b * LSE_CH + ch) * Hn + h] = s;
}

// ---------- kernel 4b: combine + MLP ----------
__global__ void __launch_bounds__(128)
finalize_kernel(const float* __restrict__ fc1w, const float* __restrict__ fc1b,
                const float* __restrict__ fc2w, const float* __restrict__ fc2b,
                float* __restrict__ out) {
    int b = blockIdx.x;
    int h = threadIdx.x;

    float M = -3.4e38f;
    #pragma unroll
    for (int ch = 0; ch < LSE_CH; ch++)
        M = fmaxf(M, g_lsem[(b * LSE_CH + ch) * Hn + h]);
    float S = 0.f;
    #pragma unroll
    for (int ch = 0; ch < LSE_CH; ch++) {
        float m = g_lsem[(b * LSE_CH + ch) * Hn + h];
        float s = g_lses[(b * LSE_CH + ch) * Hn + h];
        S += s * __expf(m - M);
    }
    float pooled = M + logf(S);

    __shared__ float ps[Hn];
    __shared__ float red[Hn];
    ps[h] = pooled;
    __syncthreads();

    float a = fc1b[h];
    #pragma unroll 8
    for (int i = 0; i < Hn; i++) a = fmaf(fc1w[h * Hn + i], ps[i], a);
    float hv = a / (1.f + __expf(-a));

    red[h] = hv * fc2w[h];
    __syncthreads();
    for (int st = 64; st > 0; st >>= 1) {
        if (h < st) red[h] += red[h + st];
        __syncthreads();
    }
    if (h == 0) out[b] = red[0] + fc2b[0];
}

// -------------------- launcher --------------------
extern "C" void kernel_launch(void* const* d_in, const int* in_sizes, int n_in,
                              void* d_out, int out_size) {
    const float* x    = (const float*)d_in[0];
    const float* Wmap = (const float*)d_in[1];
    const float* WL   = (const float*)d_in[2];
    const float* WR   = (const float*)d_in[3];
    const float* fc1w = (const float*)d_in[4];
    const float* fc1b = (const float*)d_in[5];
    const float* fc2w = (const float*)d_in[6];
    const float* fc2b = (const float*)d_in[7];
    float* out = (float*)d_out;

    double mu0  = exp(-5.0);
    double dm   = (1.0 - mu0) / 49.0;
    double beta = pow(2.0 / 50.0 * (1.0 - mu0), -2.0);
    double tbd  = 2.0 * beta * dm;
    double bdm2 = beta * dm * dm;
    double d2   = exp(-2.0 * bdm2);

    const int smem_xc = XC_CHUNK * 24 * (int)sizeof(float);   // 49152

    cudaFuncSetAttribute(xc_kernel, cudaFuncAttributeMaxDynamicSharedMemorySize, smem_xc);
    cudaFuncSetAttribute(main_kernel, cudaFuncAttributeMaxDynamicSharedMemorySize, SMEM_MAIN_TOTAL);

    pad_weights_kernel<<<NPAIR * QCH, 128>>>(WL, WR);
    xc_kernel<<<(Gn * Mn) / XC_ROWS, XC_ROWS * 12, smem_xc>>>(x, Wmap);
    main_kernel<<<(Bn * Gn) / Tn, 256, SMEM_MAIN_TOTAL>>>(
        (float)mu0, (float)dm, (float)(1.0 / dm), (float)beta,
        (float)tbd, (float)bdm2, (float)d2);
    lse_partial_kernel<<<dim3(LSE_CH, Bn), 128>>>();
    finalize_kernel<<<Bn, 128>>>(fc1w, fc1b, fc2w, fc2b, out);
}

// round 16
// speedup vs baseline: 1.0070x; 1.0070x over previous
#include <cuda_runtime.h>
#include <cuda_bf16.h>
#include <math.h>

#define Bn   8
#define Gn   1024
#define Mn   8
#define Nn   2048
#define RBFn 50
#define QCH  13     // 13 chunks of 4 r (52 padded)
#define NPAIR 28    // i<j pairs of 8 particles
#define Hn   128
#define Fn   3200
#define Tn   8      // (b,g) pairs per CTA in main kernel
#define KROW 424    // smv row stride per k: 53*8 floats
#define XC_ROWS 32
#define XC_CHUNK 512
#define LSE_CH  32

// f32x2 packed math helpers
#define FMA2(d, a, b, c) \
    asm("fma.rn.f32x2 %0, %1, %2, %3;" : "=l"(d) : "l"(a), "l"(b), "l"(c))
#define PK2(d, x) \
    asm("mov.b64 %0, {%1, %1};" : "=l"(d) : "f"(x))
#define UNPK2(lo, hi, v) \
    asm("mov.b64 {%0, %1}, %2;" : "=f"(lo), "=f"(hi) : "l"(v))

// bf16 (packed in u32) -> f32
#define BFLO(u) __uint_as_float((u) << 16)
#define BFHI(u) __uint_as_float((u) & 0xFFFF0000u)

__constant__ int c_pi[NPAIR] = {0,0,0,0,0,0,0, 1,1,1,1,1,1, 2,2,2,2,2, 3,3,3,3, 4,4,4, 5,5, 6};
__constant__ int c_pj[NPAIR] = {1,2,3,4,5,6,7, 2,3,4,5,6,7, 3,4,5,6,7, 4,5,6,7, 5,6,7, 6,7, 7};

// -------------------- scratch (static device globals) --------------------
// bf16 folded weights, L/R interleaved: [kq(364)][h(128)] as uint4
__device__ __align__(16) uint4 g_Wbf[NPAIR * QCH * Hn];
__device__ float g_xc[Bn * Gn * Mn * 3];
__device__ float g_att[Bn * Gn * Hn];
__device__ float g_lsem[Bn * LSE_CH * Hn];
__device__ float g_lses[Bn * LSE_CH * Hn];

// ---------- kernel 1: fold + repack weights to interleaved bf16 ----------
__global__ void __launch_bounds__(128)
pad_weights_kernel(const float* __restrict__ WL, const float* __restrict__ WR) {
    int kq = blockIdx.x;              // 0..363
    int k  = kq / QCH;
    int q  = kq - k * QCH;
    int h  = threadIdx.x;
    int i  = c_pi[k], j = c_pj[k];
    float vL[4], vR[4];
    #pragma unroll
    for (int rr = 0; rr < 4; rr++) {
        int r = q * 4 + rr;
        vL[rr] = 0.f; vR[rr] = 0.f;
        if (r < RBFn) {
            int fij = (i * Mn + j) * RBFn + r;
            int fji = (j * Mn + i) * RBFn + r;
            vL[rr] = WL[h * Fn + fij] - WL[h * Fn + fji];
            vR[rr] = WR[h * Fn + fij] - WR[h * Fn + fji];
        }
    }
    __nv_bfloat162 lx = __floats2bfloat162_rn(vL[0], vL[1]);
    __nv_bfloat162 ly = __floats2bfloat162_rn(vL[2], vL[3]);
    __nv_bfloat162 rx = __floats2bfloat162_rn(vR[0], vR[1]);
    __nv_bfloat162 ry = __floats2bfloat162_rn(vR[2], vR[3]);
    uint4 o;
    o.x = *(unsigned int*)&lx;
    o.y = *(unsigned int*)&ly;
    o.z = *(unsigned int*)&rx;
    o.w = *(unsigned int*)&ry;
    g_Wbf[kq * Hn + h] = o;
}

// ---------- kernel 2: xc = batched thin GEMM (f32x2, chunked) ----------
__global__ void __launch_bounds__(XC_ROWS * 12, 2)
xc_kernel(const float* __restrict__ x, const float* __restrict__ Wmap) {
    extern __shared__ float xs[];  // [XC_CHUNK][24] = 49152 B

    int row = blockIdx.x * XC_ROWS + threadIdx.x / 12;
    int c2  = threadIdx.x % 12;

    const float4* __restrict__ wrow =
        reinterpret_cast<const float4*>(Wmap) + (size_t)row * (Nn / 4);

    unsigned long long a0 = 0ull, a1 = 0ull, a2 = 0ull, a3 = 0ull;

    for (int ch = 0; ch < Nn / XC_CHUNK; ch++) {
        __syncthreads();
        for (int e = threadIdx.x; e < Bn * XC_CHUNK * 3; e += XC_ROWS * 12) {
            int b   = e / (XC_CHUNK * 3);
            int rem = e - b * (XC_CHUNK * 3);
            int n   = rem / 3;
            int d   = rem - n * 3;
            xs[n * 24 + b * 3 + d] = x[(b * Nn + ch * XC_CHUNK + n) * 3 + d];
        }
        __syncthreads();

        const float4* wch = wrow + ch * (XC_CHUNK / 4);
        #pragma unroll 8
        for (int n4 = 0; n4 < XC_CHUNK / 4; n4++) {
            float4 w = __ldg(wch + n4);
            const float* xp = xs + n4 * 96 + c2 * 2;
            unsigned long long s0 = *(const unsigned long long*)(xp);
            unsigned long long s1 = *(const unsigned long long*)(xp + 24);
            unsigned long long s2 = *(const unsigned long long*)(xp + 48);
            unsigned long long s3 = *(const unsigned long long*)(xp + 72);
            unsigned long long w0, w1, w2, w3;
            PK2(w0, w.x); PK2(w1, w.y); PK2(w2, w.z); PK2(w3, w.w);
            FMA2(a0, w0, s0, a0);
            FMA2(a1, w1, s1, a1);
            FMA2(a2, w2, s2, a2);
            FMA2(a3, w3, s3, a3);
        }
    }

    float a0lo, a0hi, a1lo, a1hi, a2lo, a2hi, a3lo, a3hi;
    UNPK2(a0lo, a0hi, a0);
    UNPK2(a1lo, a1hi, a1);
    UNPK2(a2lo, a2hi, a2);
    UNPK2(a3lo, a3hi, a3);
    float accA = (a0lo + a1lo) + (a2lo + a3lo);
    float accB = (a0hi + a1hi) + (a2hi + a3hi);

    int cA = c2 * 2;
    int bA = cA / 3, dA = cA - bA * 3;
    g_xc[((size_t)bA * (Gn * Mn) + row) * 3 + dA] = accA;
    int cB = cA + 1;
    int bB = cB / 3, dB = cB - bB * 3;
    g_xc[((size_t)bB * (Gn * Mn) + row) * 3 + dB] = accB;
}

// -------------------- kernel 3: main fused kernel --------------------
// 512 threads = h(128) x pair-half(2) x t-half(2); Tn=8; 2 CTA/SM
// (8 warps/SMSP). Each thread: 14 pairs, 4 t, both L and R.
// acc 12 u64 + ws 4 u64 ~= 55-60 regs -> fits the 64-reg cap of (512,2).
__global__ void __launch_bounds__(512, 2)
main_kernel(float MU0f, float DMf, float INVDMf, float BETAf,
            float TBDf, float BDM2f, float D2f) {
    extern __shared__ float sh[];
    float* smv = sh;                          // 28*424 = 11872 floats
    float* dl  = sh + NPAIR * KROW;           // 28*24  = 672
    float* xcs = dl + NPAIR * 24;             // 192   (50944 B total)

    int tid = threadIdx.x;
    int bg0 = blockIdx.x * Tn;

    for (int e = tid; e < Tn * 24; e += blockDim.x)
        xcs[e] = g_xc[bg0 * 24 + e];
    __syncthreads();

    // ---- Phase A: thread = (k, t); geometric recurrence from peak ----
    if (tid < Tn * NPAIR) {
        int k = tid >> 3;
        int t = tid & 7;
        int i = c_pi[k], j = c_pj[k];
        const float* xt = xcs + t * 24;
        float dx = xt[j * 3 + 0] - xt[i * 3 + 0];
        float dy = xt[j * 3 + 1] - xt[i * 3 + 1];
        float dz = xt[j * 3 + 2] - xt[i * 3 + 2];
        float* drow = dl + k * 24 + t;
        drow[0]  = dx;
        drow[8]  = dy;
        drow[16] = dz;

        float dn  = sqrtf(fmaf(dx, dx, fmaf(dy, dy, dz * dz)) + 1e-5f);
        float uu  = __expf(-dn);
        float cut = (dn < 5.0f)
                  ? 0.5f * (__cosf(dn * 0.6283185307179586f) + 1.0f)
                  : 0.0f;
        float dd   = dn + 1e-5f;
        float coef = cut / (dd * dd);

        float up = uu - MU0f;
        int rs = (int)rintf(up * INVDMf);
        rs = rs < 0 ? 0 : (rs > 49 ? 49 : rs);
        float du = up - (float)rs * DMf;
        float t0 = coef * __expf(-BETAf * du * du);
        float s  = TBDf * up - BDM2f * (float)(2 * rs + 1);
        float qu = __expf(s);
        float qd = __expf(-s) * D2f;

        float* srow = smv + k * KROW + t;
        srow[rs * 8] = t0;
        float tv = t0;
        for (int r = rs + 1; r < RBFn; r++) {
            tv *= qu; qu *= D2f;
            srow[r * 8] = tv;
        }
        tv = t0;
        for (int r = rs - 1; r >= 0; r--) {
            tv *= qd; qd *= D2f;
            srow[r * 8] = tv;
        }
        srow[50 * 8] = 0.f;
        srow[51 * 8] = 0.f;
    }
    __syncthreads();

    // ---- Phase B: 14 pairs, both sides, 4 t per thread ----
    int h  = tid & 127;
    int ph = (tid >> 7) & 1;   // pair half: k in [ph*14, ph*14+14)
    int th = tid >> 8;         // t half: t in [th*4, th*4+4)

    const uint4* __restrict__ wb = g_Wbf + h;

    unsigned long long acc2L[2][3] = {{0ull}}, acc2R[2][3] = {{0ull}};

    int k0 = ph * (NPAIR / 2);
    #pragma unroll 2
    for (int k = k0; k < k0 + NPAIR / 2; k++) {
        unsigned long long ws2L[2] = {0ull, 0ull};
        unsigned long long ws2R[2] = {0ull, 0ull};
        const float* sk = smv + k * KROW + th * 4;

        #pragma unroll
        for (int q = 0; q < QCH; q++) {
            uint4 wp = __ldg(wb + (size_t)(k * QCH + q) * Hn);

            #define DO_RR(RR, AV, CV)                                          \
            {                                                                  \
                ulonglong2 s = *(const ulonglong2*)(sk + (q * 4 + (RR)) * 8);  \
                unsigned long long a2, c2;                                     \
                PK2(a2, (AV)); PK2(c2, (CV));                                  \
                FMA2(ws2L[0], a2, s.x, ws2L[0]);                               \
                FMA2(ws2L[1], a2, s.y, ws2L[1]);                               \
                FMA2(ws2R[0], c2, s.x, ws2R[0]);                               \
                FMA2(ws2R[1], c2, s.y, ws2R[1]);                               \
            }
            DO_RR(0, BFLO(wp.x), BFLO(wp.z))
            DO_RR(1, BFHI(wp.x), BFHI(wp.z))
            DO_RR(2, BFLO(wp.y), BFLO(wp.w))
            DO_RR(3, BFHI(wp.y), BFHI(wp.w))
            #undef DO_RR
        }

        const float* dk = dl + k * 24 + th * 4;
        #pragma unroll
        for (int d = 0; d < 3; d++) {
            ulonglong2 dd = *(const ulonglong2*)(dk + d * 8);
            FMA2(acc2L[0][d], ws2L[0], dd.x, acc2L[0][d]);
            FMA2(acc2L[1][d], ws2L[1], dd.y, acc2L[1][d]);
            FMA2(acc2R[0][d], ws2R[0], dd.x, acc2R[0][d]);
            FMA2(acc2R[1][d], ws2R[1], dd.y, acc2R[1][d]);
        }
    }

    // ---- cross-ph reduction via padded smem (stride 25) ----
    __syncthreads();
    float* red = smv;   // 2*128*25 = 6400 floats <= 11872
    if (ph == 1) {
        float* r0 = red + (th * Hn + h) * 25;
        #pragma unroll
        for (int u = 0; u < 2; u++) {
            #pragma unroll
            for (int d = 0; d < 3; d++) {
                float lo, hi;
                UNPK2(lo, hi, acc2L[u][d]);
                r0[(2 * u) * 6 + d]     = lo;
                r0[(2 * u + 1) * 6 + d] = hi;
                UNPK2(lo, hi, acc2R[u][d]);
                r0[(2 * u) * 6 + 3 + d]     = lo;
                r0[(2 * u + 1) * 6 + 3 + d] = hi;
            }
        }
    }
    __syncthreads();
    if (ph == 0) {
        const float* r0 = red + (th * Hn + h) * 25;
        #pragma unroll
        for (int u = 0; u < 2; u++) {
            float L[2][3], R[2][3];
            #pragma unroll
            for (int d = 0; d < 3; d++) {
                UNPK2(L[0][d], L[1][d], acc2L[u][d]);
                UNPK2(R[0][d], R[1][d], acc2R[u][d]);
            }
            #pragma unroll
            for (int e = 0; e < 2; e++) {
                int tl = 2 * u + e;
                float L0 = L[e][0] + r0[tl * 6 + 0];
                float L1 = L[e][1] + r0[tl * 6 + 1];
                float L2 = L[e][2] + r0[tl * 6 + 2];
                float R0 = R[e][0] + r0[tl * 6 + 3];
                float R1 = R[e][1] + r0[tl * 6 + 4];
                float R2 = R[e][2] + r0[tl * 6 + 5];
                float att = fmaf(L0, R0, fmaf(L1, R1, L2 * R2)) + 1e-5f;
                g_att[(size_t)(bg0 + th * 4 + tl) * Hn + h] = att;
            }
        }
    }
}

// ---------- kernel 4a: partial logsumexp ----------
__global__ void __launch_bounds__(128)
lse_partial_kernel() {
    int b  = blockIdx.y;
    int ch = blockIdx.x;
    int h  = threadIdx.x;
    const int GPC = Gn / LSE_CH;
    const float* base = g_att + ((size_t)b * Gn + ch * GPC) * Hn + h;

    float v[GPC];
    #pragma unroll
    for (int i = 0; i < GPC; i++) v[i] = base[(size_t)i * Hn];

    float mx = v[0];
    #pragma unroll
    for (int i = 1; i < GPC; i++) mx = fmaxf(mx, v[i]);
    float s = 0.f;
    #pragma unroll
    for (int i = 0; i < GPC; i++) s += __expf(v[i] - mx);

    g_lsem[(b * LSE_CH + ch) * Hn + h] = mx;
    g_lses[(b * LSE_CH + ch) * Hn + h] = s;
}

// ---------- kernel 4b: combine + MLP ----------
__global__ void __launch_bounds__(128)
finalize_kernel(const float* __restrict__ fc1w, const float* __restrict__ fc1b,
                const float* __restrict__ fc2w, const float* __restrict__ fc2b,
                float* __restrict__ out) {
    int b = blockIdx.x;
    int h = threadIdx.x;

    float M = -3.4e38f;
    #pragma unroll
    for (int ch = 0; ch < LSE_CH; ch++)
        M = fmaxf(M, g_lsem[(b * LSE_CH + ch) * Hn + h]);
    float S = 0.f;
    #pragma unroll
    for (int ch = 0; ch < LSE_CH; ch++) {
        float m = g_lsem[(b * LSE_CH + ch) * Hn + h];
        float s = g_lses[(b * LSE_CH + ch) * Hn + h];
        S += s * __expf(m - M);
    }
    float pooled = M + logf(S);

    __shared__ float ps[Hn];
    __shared__ float red[Hn];
    ps[h] = pooled;
    __syncthreads();

    float a = fc1b[h];
    #pragma unroll 8
    for (int i = 0; i < Hn; i++) a = fmaf(fc1w[h * Hn + i], ps[i], a);
    float hv = a / (1.f + __expf(-a));

    red[h] = hv * fc2w[h];
    __syncthreads();
    for (int st = 64; st > 0; st >>= 1) {
        if (h < st) red[h] += red[h + st];
        __syncthreads();
    }
    if (h == 0) out[b] = red[0] + fc2b[0];
}

// -------------------- launcher --------------------
extern "C" void kernel_launch(void* const* d_in, const int* in_sizes, int n_in,
                              void* d_out, int out_size) {
    const float* x    = (const float*)d_in[0];
    const float* Wmap = (const float*)d_in[1];
    const float* WL   = (const float*)d_in[2];
    const float* WR   = (const float*)d_in[3];
    const float* fc1w = (const float*)d_in[4];
    const float* fc1b = (const float*)d_in[5];
    const float* fc2w = (const float*)d_in[6];
    const float* fc2b = (const float*)d_in[7];
    float* out = (float*)d_out;

    double mu0  = exp(-5.0);
    double dm   = (1.0 - mu0) / 49.0;
    double beta = pow(2.0 / 50.0 * (1.0 - mu0), -2.0);
    double tbd  = 2.0 * beta * dm;
    double bdm2 = beta * dm * dm;
    double d2   = exp(-2.0 * bdm2);

    const int smem_xc   = XC_CHUNK * 24 * (int)sizeof(float);   // 49152
    const int smem_main = (NPAIR * KROW + NPAIR * 24 + Tn * 24) * (int)sizeof(float);

    cudaFuncSetAttribute(xc_kernel, cudaFuncAttributeMaxDynamicSharedMemorySize, smem_xc);
    cudaFuncSetAttribute(main_kernel, cudaFuncAttributeMaxDynamicSharedMemorySize, smem_main);

    pad_weights_kernel<<<NPAIR * QCH, 128>>>(WL, WR);
    xc_kernel<<<(Gn * Mn) / XC_ROWS, XC_ROWS * 12, smem_xc>>>(x, Wmap);
    main_kernel<<<(Bn * Gn) / Tn, 512, smem_main>>>(
        (float)mu0, (float)dm, (float)(1.0 / dm), (float)beta,
        (float)tbd, (float)bdm2, (float)d2);
    lse_partial_kernel<<<dim3(LSE_CH, Bn), 128>>>();
    finalize_kernel<<<Bn, 128>>>(fc1w, fc1b, fc2w, fc2b, out);
}

// round 17
// speedup vs baseline: 1.0832x; 1.0756x over previous
#include <cuda_runtime.h>
#include <cuda_bf16.h>
#include <math.h>

#define Bn   8
#define Gn   1024
#define Mn   8
#define Nn   2048
#define RBFn 50
#define QCH  13     // 13 chunks of 4 r (52 padded)
#define NPAIR 28    // i<j pairs of 8 particles
#define Hn   128
#define Fn   3200
#define Tn   8      // (b,g) pairs per CTA in main kernel
#define TROW 416    // smv2 stride per k: 8 t * 52 r
#define WQ   5      // window chunks (20 r) per (k,t)
#define XC_ROWS 32
#define XC_CHUNK 512
#define LSE_CH  32

// f32x2 packed math helpers (xc kernel)
#define FMA2(d, a, b, c) \
    asm("fma.rn.f32x2 %0, %1, %2, %3;" : "=l"(d) : "l"(a), "l"(b), "l"(c))
#define PK2(d, x) \
    asm("mov.b64 %0, {%1, %1};" : "=l"(d) : "f"(x))
#define UNPK2(lo, hi, v) \
    asm("mov.b64 {%0, %1}, %2;" : "=f"(lo), "=f"(hi) : "l"(v))

// bf16 (packed in u32) -> f32
#define BFLO(u) __uint_as_float((u) << 16)
#define BFHI(u) __uint_as_float((u) & 0xFFFF0000u)

__constant__ int c_pi[NPAIR] = {0,0,0,0,0,0,0, 1,1,1,1,1,1, 2,2,2,2,2, 3,3,3,3, 4,4,4, 5,5, 6};
__constant__ int c_pj[NPAIR] = {1,2,3,4,5,6,7, 2,3,4,5,6,7, 3,4,5,6,7, 4,5,6,7, 5,6,7, 6,7, 7};

// -------------------- scratch (static device globals) --------------------
// bf16 folded weights, L/R interleaved: [kq(364)][h(128)] as uint4
// x = L(r0)|L(r1)<<16, y = L(r2)|L(r3)<<16, z/w = same for R
__device__ __align__(16) uint4 g_Wbf[NPAIR * QCH * Hn];
__device__ float g_xc[Bn * Gn * Mn * 3];
__device__ float g_att[Bn * Gn * Hn];
__device__ float g_lsem[Bn * LSE_CH * Hn];
__device__ float g_lses[Bn * LSE_CH * Hn];

// ---------- kernel 1: fold + repack weights to interleaved bf16 ----------
__global__ void __launch_bounds__(128)
pad_weights_kernel(const float* __restrict__ WL, const float* __restrict__ WR) {
    int kq = blockIdx.x;              // 0..363
    int k  = kq / QCH;
    int q  = kq - k * QCH;
    int h  = threadIdx.x;
    int i  = c_pi[k], j = c_pj[k];
    float vL[4], vR[4];
    #pragma unroll
    for (int rr = 0; rr < 4; rr++) {
        int r = q * 4 + rr;
        vL[rr] = 0.f; vR[rr] = 0.f;
        if (r < RBFn) {
            int fij = (i * Mn + j) * RBFn + r;
            int fji = (j * Mn + i) * RBFn + r;
            vL[rr] = WL[h * Fn + fij] - WL[h * Fn + fji];
            vR[rr] = WR[h * Fn + fij] - WR[h * Fn + fji];
        }
    }
    __nv_bfloat162 lx = __floats2bfloat162_rn(vL[0], vL[1]);
    __nv_bfloat162 ly = __floats2bfloat162_rn(vL[2], vL[3]);
    __nv_bfloat162 rx = __floats2bfloat162_rn(vR[0], vR[1]);
    __nv_bfloat162 ry = __floats2bfloat162_rn(vR[2], vR[3]);
    uint4 o;
    o.x = *(unsigned int*)&lx;
    o.y = *(unsigned int*)&ly;
    o.z = *(unsigned int*)&rx;
    o.w = *(unsigned int*)&ry;
    g_Wbf[kq * Hn + h] = o;
}

// ---------- kernel 2: xc = batched thin GEMM (f32x2, chunked) ----------
__global__ void __launch_bounds__(XC_ROWS * 12, 2)
xc_kernel(const float* __restrict__ x, const float* __restrict__ Wmap) {
    extern __shared__ float xs[];  // [XC_CHUNK][24] = 49152 B

    int row = blockIdx.x * XC_ROWS + threadIdx.x / 12;
    int c2  = threadIdx.x % 12;

    const float4* __restrict__ wrow =
        reinterpret_cast<const float4*>(Wmap) + (size_t)row * (Nn / 4);

    unsigned long long a0 = 0ull, a1 = 0ull, a2 = 0ull, a3 = 0ull;

    for (int ch = 0; ch < Nn / XC_CHUNK; ch++) {
        __syncthreads();
        for (int e = threadIdx.x; e < Bn * XC_CHUNK * 3; e += XC_ROWS * 12) {
            int b   = e / (XC_CHUNK * 3);
            int rem = e - b * (XC_CHUNK * 3);
            int n   = rem / 3;
            int d   = rem - n * 3;
            xs[n * 24 + b * 3 + d] = x[(b * Nn + ch * XC_CHUNK + n) * 3 + d];
        }
        __syncthreads();

        const float4* wch = wrow + ch * (XC_CHUNK / 4);
        #pragma unroll 8
        for (int n4 = 0; n4 < XC_CHUNK / 4; n4++) {
            float4 w = __ldg(wch + n4);
            const float* xp = xs + n4 * 96 + c2 * 2;
            unsigned long long s0 = *(const unsigned long long*)(xp);
            unsigned long long s1 = *(const unsigned long long*)(xp + 24);
            unsigned long long s2 = *(const unsigned long long*)(xp + 48);
            unsigned long long s3 = *(const unsigned long long*)(xp + 72);
            unsigned long long w0, w1, w2, w3;
            PK2(w0, w.x); PK2(w1, w.y); PK2(w2, w.z); PK2(w3, w.w);
            FMA2(a0, w0, s0, a0);
            FMA2(a1, w1, s1, a1);
            FMA2(a2, w2, s2, a2);
            FMA2(a3, w3, s3, a3);
        }
    }

    float a0lo, a0hi, a1lo, a1hi, a2lo, a2hi, a3lo, a3hi;
    UNPK2(a0lo, a0hi, a0);
    UNPK2(a1lo, a1hi, a1);
    UNPK2(a2lo, a2hi, a2);
    UNPK2(a3lo, a3hi, a3);
    float accA = (a0lo + a1lo) + (a2lo + a3lo);
    float accB = (a0hi + a1hi) + (a2hi + a3hi);

    int cA = c2 * 2;
    int bA = cA / 3, dA = cA - bA * 3;
    g_xc[((size_t)bA * (Gn * Mn) + row) * 3 + dA] = accA;
    int cB = cA + 1;
    int bB = cB / 3, dB = cB - bB * 3;
    g_xc[((size_t)bB * (Gn * Mn) + row) * 3 + dB] = accB;
}

// -------------------- kernel 3: main fused kernel (banded RBF) -----------
// 256 threads = h(128) x pair-half(2); Tn=8; 2 CTA/SM.
// Phase A: sm is a narrow Gaussian in r (sigma ~1.4 grid steps) -> only a
// 20-wide window [4*q0, 4*q0+19] per (k,t) is nonzero above 5.6e-8.
// Phase B: scalar-FFMA over the window only (2.6x fewer MACs; scalar FFMA
// has the same MAC rate as packed f32x2 on this chip). Window bounds are
// (k,t)-uniform across the warp -> no divergence.
__global__ void __launch_bounds__(256, 2)
main_kernel(float MU0f, float DMf, float INVDMf, float BETAf,
            float TBDf, float BDM2f, float D2f) {
    extern __shared__ float sh[];
    float* smv = sh;                            // [28][8][52] = 11648 floats
    float* dl  = sh + NPAIR * TROW;             // [28][3][8]  = 672
    float* xcs = dl + NPAIR * 24;               // 192
    int*   qs  = (int*)(xcs + Tn * 24);         // [28][8]     = 224 ints

    int tid = threadIdx.x;
    int bg0 = blockIdx.x * Tn;

    for (int e = tid; e < Tn * 24; e += blockDim.x)
        xcs[e] = g_xc[bg0 * 24 + e];
    __syncthreads();

    // ---- Phase A: thread = (k, t); geometric recurrence + window start ----
    if (tid < Tn * NPAIR) {
        int k = tid >> 3;
        int t = tid & 7;
        int i = c_pi[k], j = c_pj[k];
        const float* xt = xcs + t * 24;
        float dx = xt[j * 3 + 0] - xt[i * 3 + 0];
        float dy = xt[j * 3 + 1] - xt[i * 3 + 1];
        float dz = xt[j * 3 + 2] - xt[i * 3 + 2];
        float* drow = dl + k * 24 + t;
        drow[0]  = dx;
        drow[8]  = dy;
        drow[16] = dz;

        float dn  = sqrtf(fmaf(dx, dx, fmaf(dy, dy, dz * dz)) + 1e-5f);
        float uu  = __expf(-dn);
        float cut = (dn < 5.0f)
                  ? 0.5f * (__cosf(dn * 0.6283185307179586f) + 1.0f)
                  : 0.0f;
        float dd   = dn + 1e-5f;
        float coef = cut / (dd * dd);

        float up = uu - MU0f;
        int rs = (int)rintf(up * INVDMf);
        rs = rs < 0 ? 0 : (rs > 49 ? 49 : rs);
        float du = up - (float)rs * DMf;
        float t0 = coef * __expf(-BETAf * du * du);
        float s  = TBDf * up - BDM2f * (float)(2 * rs + 1);
        float qu = __expf(s);
        float qd = __expf(-s) * D2f;

        // window start (in 4-r chunks): covers at least rs-8 .. rs+8
        int a = rs - 8;
        int q0 = (a < 0) ? 0 : (a >> 2);
        if (q0 > 8) q0 = 8;
        qs[k * 8 + t] = q0;

        float* srow = smv + (k * 8 + t) * 52;   // [k][t][r]
        srow[rs] = t0;
        float tv = t0;
        for (int r = rs + 1; r < RBFn; r++) {
            tv *= qu; qu *= D2f;
            srow[r] = tv;
        }
        tv = t0;
        for (int r = rs - 1; r >= 0; r--) {
            tv *= qd; qd *= D2f;
            srow[r] = tv;
        }
        srow[50] = 0.f;
        srow[51] = 0.f;
    }
    __syncthreads();

    // ---- Phase B: banded scalar-FFMA dual projections, pairs split 14/14 --
    int h  = tid & 127;
    int ph = tid >> 7;

    float accL[Tn][3] = {{0.f}}, accR[Tn][3] = {{0.f}};

    int k0 = ph * (NPAIR / 2);
    for (int k = k0; k < k0 + NPAIR / 2; k++) {
        const uint4* __restrict__ wk = g_Wbf + k * QCH * Hn + h;
        const float* sk = smv + k * 8 * 52;
        const float* dk = dl + k * 24;

        #pragma unroll
        for (int t = 0; t < Tn; t++) {
            int q0 = qs[k * 8 + t];                 // warp-uniform
            const float*  sr = sk + t * 52 + 4 * q0;
            const uint4*  wr = wk + q0 * Hn;

            float wsL = 0.f, wsR = 0.f;
            #pragma unroll
            for (int c = 0; c < WQ; c++) {
                uint4  wp = __ldg(wr + c * Hn);
                float4 s  = *(const float4*)(sr + 4 * c);
                wsL = fmaf(BFLO(wp.x), s.x, wsL);
                wsR = fmaf(BFLO(wp.z), s.x, wsR);
                wsL = fmaf(BFHI(wp.x), s.y, wsL);
                wsR = fmaf(BFHI(wp.z), s.y, wsR);
                wsL = fmaf(BFLO(wp.y), s.z, wsL);
                wsR = fmaf(BFLO(wp.w), s.z, wsR);
                wsL = fmaf(BFHI(wp.y), s.w, wsL);
                wsR = fmaf(BFHI(wp.w), s.w, wsR);
            }

            float d0 = dk[t], d1 = dk[8 + t], d2 = dk[16 + t];
            accL[t][0] = fmaf(wsL, d0, accL[t][0]);
            accL[t][1] = fmaf(wsL, d1, accL[t][1]);
            accL[t][2] = fmaf(wsL, d2, accL[t][2]);
            accR[t][0] = fmaf(wsR, d0, accR[t][0]);
            accR[t][1] = fmaf(wsR, d1, accR[t][1]);
            accR[t][2] = fmaf(wsR, d2, accR[t][2]);
        }
    }

    // ---- cross-half reduction (reuse smv; stride 49) ----
    __syncthreads();
    float* red = smv;   // 128*49 = 6272 floats <= 11648
    if (ph == 1) {
        float* r0 = red + h * 49;
        #pragma unroll
        for (int t = 0; t < Tn; t++) {
            #pragma unroll
            for (int d = 0; d < 3; d++) {
                r0[t * 6 + d]     = accL[t][d];
                r0[t * 6 + 3 + d] = accR[t][d];
            }
        }
    }
    __syncthreads();
    if (ph == 0) {
        const float* r0 = red + h * 49;
        #pragma unroll
        for (int t = 0; t < Tn; t++) {
            float L0 = accL[t][0] + r0[t * 6 + 0];
            float L1 = accL[t][1] + r0[t * 6 + 1];
            float L2 = accL[t][2] + r0[t * 6 + 2];
            float R0 = accR[t][0] + r0[t * 6 + 3];
            float R1 = accR[t][1] + r0[t * 6 + 4];
            float R2 = accR[t][2] + r0[t * 6 + 5];
            float att = fmaf(L0, R0, fmaf(L1, R1, L2 * R2)) + 1e-5f;
            g_att[(size_t)(bg0 + t) * Hn + h] = att;
        }
    }
}

// ---------- kernel 4a: partial logsumexp ----------
__global__ void __launch_bounds__(128)
lse_partial_kernel() {
    int b  = blockIdx.y;
    int ch = blockIdx.x;
    int h  = threadIdx.x;
    const int GPC = Gn / LSE_CH;
    const float* base = g_att + ((size_t)b * Gn + ch * GPC) * Hn + h;

    float v[GPC];
    #pragma unroll
    for (int i = 0; i < GPC; i++) v[i] = base[(size_t)i * Hn];

    float mx = v[0];
    #pragma unroll
    for (int i = 1; i < GPC; i++) mx = fmaxf(mx, v[i]);
    float s = 0.f;
    #pragma unroll
    for (int i = 0; i < GPC; i++) s += __expf(v[i] - mx);

    g_lsem[(b * LSE_CH + ch) * Hn + h] = mx;
    g_lses[(b * LSE_CH + ch) * Hn + h] = s;
}

// ---------- kernel 4b: combine + MLP ----------
__global__ void __launch_bounds__(128)
finalize_kernel(const float* __restrict__ fc1w, const float* __restrict__ fc1b,
                const float* __restrict__ fc2w, const float* __restrict__ fc2b,
                float* __restrict__ out) {
    int b = blockIdx.x;
    int h = threadIdx.x;

    float M = -3.4e38f;
    #pragma unroll
    for (int ch = 0; ch < LSE_CH; ch++)
        M = fmaxf(M, g_lsem[(b * LSE_CH + ch) * Hn + h]);
    float S = 0.f;
    #pragma unroll
    for (int ch = 0; ch < LSE_CH; ch++) {
        float m = g_lsem[(b * LSE_CH + ch) * Hn + h];
        float s = g_lses[(b * LSE_CH + ch) * Hn + h];
        S += s * __expf(m - M);
    }
    float pooled = M + logf(S);

    __shared__ float ps[Hn];
    __shared__ float red[Hn];
    ps[h] = pooled;
    __syncthreads();

    float a = fc1b[h];
    #pragma unroll 8
    for (int i = 0; i < Hn; i++) a = fmaf(fc1w[h * Hn + i], ps[i], a);
    float hv = a / (1.f + __expf(-a));

    red[h] = hv * fc2w[h];
    __syncthreads();
    for (int st = 64; st > 0; st >>= 1) {
        if (h < st) red[h] += red[h + st];
        __syncthreads();
    }
    if (h == 0) out[b] = red[0] + fc2b[0];
}

// -------------------- launcher --------------------
extern "C" void kernel_launch(void* const* d_in, const int* in_sizes, int n_in,
                              void* d_out, int out_size) {
    const float* x    = (const float*)d_in[0];
    const float* Wmap = (const float*)d_in[1];
    const float* WL   = (const float*)d_in[2];
    const float* WR   = (const float*)d_in[3];
    const float* fc1w = (const float*)d_in[4];
    const float* fc1b = (const float*)d_in[5];
    const float* fc2w = (const float*)d_in[6];
    const float* fc2b = (const float*)d_in[7];
    float* out = (float*)d_out;

    double mu0  = exp(-5.0);
    double dm   = (1.0 - mu0) / 49.0;
    double beta = pow(2.0 / 50.0 * (1.0 - mu0), -2.0);
    double tbd  = 2.0 * beta * dm;
    double bdm2 = beta * dm * dm;
    double d2   = exp(-2.0 * bdm2);

    const int smem_xc   = XC_CHUNK * 24 * (int)sizeof(float);   // 49152
    const int smem_main = (NPAIR * TROW + NPAIR * 24 + Tn * 24 + NPAIR * Tn)
                          * (int)sizeof(float);                  // 50944

    cudaFuncSetAttribute(xc_kernel, cudaFuncAttributeMaxDynamicSharedMemorySize, smem_xc);
    cudaFuncSetAttribute(main_kernel, cudaFuncAttributeMaxDynamicSharedMemorySize, smem_main);

    pad_weights_kernel<<<NPAIR * QCH, 128>>>(WL, WR);
    xc_kernel<<<(Gn * Mn) / XC_ROWS, XC_ROWS * 12, smem_xc>>>(x, Wmap);
    main_kernel<<<(Bn * Gn) / Tn, 256, smem_main>>>(
        (float)mu0, (float)dm, (float)(1.0 / dm), (float)beta,
        (float)tbd, (float)bdm2, (float)d2);
    lse_partial_kernel<<<dim3(LSE_CH, Bn), 128>>>();
    finalize_kernel<<<Bn, 128>>>(fc1w, fc1b, fc2w, fc2b, out);
}